// round 4
// baseline (speedup 1.0000x reference)
#include <cuda_runtime.h>

#define HH 128
#define WW 128
#define CC 16
#define FF 16
#define CF (CC * FF)
#define NB 2
#define SNX 32
#define SNY 32

// ratio[b][snx][sny][c*16+f] : 2*32*32*256 floats = 2 MB
__device__ float g_ratio[(size_t)NB * SNX * SNY * CF];

// ---------------------------------------------------------------------------
// Kernel 1: per 2x2 patch quad, compute ratio = divide_no_nan(kp, diag)
// for the 4 patches (2I+a, 2J+b). Union extent: rows 8I-2..8I+9, cols 8J-2..8J+9.
// Thread t owns cf index t (c = t>>4, f = t&15): accumulators stay in-thread.
// ---------------------------------------------------------------------------
__global__ __launch_bounds__(256) void ratio_kernel(
    const float* __restrict__ pet, const float* __restrict__ bfeat)
{
    __shared__ float pet_s[12 * 12 * CC];   // 9 KB

    const int J  = blockIdx.x;
    const int I  = blockIdx.y;
    const int bz = blockIdx.z;
    const int t  = threadIdx.x;
    const int c  = t >> 4;

    const int r0 = 8 * I - 2;
    const int c0 = 8 * J - 2;

    // stage pet for the 12x12 union (zero outside image)
    for (int idx = t; idx < 12 * 12 * CC; idx += 256) {
        int pix = idx >> 4, cc = idx & 15;
        int u = pix / 12, v = pix - u * 12;
        int r = r0 + u, col = c0 + v;
        float val = 0.f;
        if ((unsigned)r < HH && (unsigned)col < WW)
            val = pet[((bz * HH + r) * WW + col) * CC + cc];
        pet_s[idx] = val;
    }
    __syncthreads();

    float d00 = 0.f, d01 = 0.f, d10 = 0.f, d11 = 0.f;
    float k00 = 0.f, k01 = 0.f, k10 = 0.f, k11 = 0.f;
    const float* bb = bfeat + (size_t)bz * HH * WW * CF + t;

    for (int u = 0; u < 12; u++) {
        int r = r0 + u;
        bool rowok = (unsigned)r < HH;
        float rd0 = 0.f, rd1 = 0.f, rk0 = 0.f, rk1 = 0.f;
#pragma unroll
        for (int v = 0; v < 12; v++) {
            int col = c0 + v;
            float bv = 0.f;
            if (rowok && (unsigned)col < WW)
                bv = __ldg(bb + (r * WW + col) * CF);
            float pv = pet_s[(u * 12 + v) * CC + c];
            float pb = pv * bv;
            if (v < 8)  { rd0 += bv; rk0 += pb; }
            if (v >= 4) { rd1 += bv; rk1 += pb; }
        }
        if (u < 8)  { d00 += rd0; d01 += rd1; k00 += rk0; k01 += rk1; }
        if (u >= 4) { d10 += rd0; d11 += rd1; k10 += rk0; k11 += rk1; }
    }

    // divide_no_nan and store 4 ratios
    float rat00 = (d00 != 0.f) ? (k00 / d00) : 0.f;
    float rat01 = (d01 != 0.f) ? (k01 / d01) : 0.f;
    float rat10 = (d10 != 0.f) ? (k10 / d10) : 0.f;
    float rat11 = (d11 != 0.f) ? (k11 / d11) : 0.f;

    const int snx = 2 * I, sny = 2 * J;
    float* rp = g_ratio + (((size_t)bz * SNX + snx) * SNY + sny) * CF + t;
    rp[0]                = rat00;   // (snx,   sny)
    rp[CF]               = rat01;   // (snx,   sny+1)
    rp[(size_t)SNY * CF] = rat10;   // (snx+1, sny)
    rp[(size_t)(SNY + 1) * CF] = rat11;
}

// ---------------------------------------------------------------------------
// Kernel 2: out(x,y,c) = 0.25 * sum_f b[x,y,c,f] * S(c,f)
// Tile (a, a2): x = 4a-2+i, y = 4a2-2+j, i,j in 0..3 (guarded).
// S = sum of ratio over snx in {a-1,a} ∩ [0,31], sny in {a2-1,a2} ∩ [0,31].
// ---------------------------------------------------------------------------
__global__ __launch_bounds__(256) void apply_kernel(
    const float* __restrict__ bfeat, float* __restrict__ out)
{
    __shared__ float S[CF];   // layout [f*16 + c] -> conflict-free broadcast reads

    const int a2 = blockIdx.x;   // y-block, 0..32
    const int a  = blockIdx.y;   // x-block, 0..32
    const int bz = blockIdx.z;
    const int t  = threadIdx.x;

    // accumulate ratio vectors for valid covering patches
    {
        float acc = 0.f;
#pragma unroll
        for (int da = 0; da < 2; da++) {
            int snx = a - 1 + da;
            if ((unsigned)snx >= SNX) continue;
#pragma unroll
            for (int db = 0; db < 2; db++) {
                int sny = a2 - 1 + db;
                if ((unsigned)sny >= SNY) continue;
                acc += g_ratio[(((size_t)bz * SNX + snx) * SNY + sny) * CF + t];
            }
        }
        int c = t >> 4, f = t & 15;
        S[f * CC + c] = acc;     // transpose store (one-time)
    }
    __syncthreads();

    const int pix = t >> 4;      // 0..15 -> (i,j) in 4x4
    const int c2  = t & 15;
    const int i = pix >> 2, j = pix & 3;
    const int x = 4 * a - 2 + i;
    const int y = 4 * a2 - 2 + j;

    if ((unsigned)x < HH && (unsigned)y < WW) {
        const float4* bp = (const float4*)(bfeat
            + ((size_t)(bz * HH + x) * WW + y) * CF + c2 * FF);
        float dot = 0.f;
#pragma unroll
        for (int q = 0; q < 4; q++) {
            float4 bv = bp[q];
            dot = fmaf(bv.x, S[(4 * q + 0) * CC + c2],
                  fmaf(bv.y, S[(4 * q + 1) * CC + c2],
                  fmaf(bv.z, S[(4 * q + 2) * CC + c2],
                  fmaf(bv.w, S[(4 * q + 3) * CC + c2], dot))));
        }
        out[((bz * HH + x) * WW + y) * CC + c2] = 0.25f * dot;
    }
}

extern "C" void kernel_launch(void* const* d_in, const int* in_sizes, int n_in,
                              void* d_out, int out_size)
{
    // Input order per reference signature: mr (unused), pet, b, px, py, sx, sy
    const float* pet   = (const float*)d_in[1];
    const float* bfeat = (const float*)d_in[2];

    dim3 grid1(SNY / 2, SNX / 2, NB);       // 16 x 16 x 2 quads
    ratio_kernel<<<grid1, 256>>>(pet, bfeat);

    dim3 grid2(33, 33, NB);                  // 33 x 33 output tiles
    apply_kernel<<<grid2, 256>>>(bfeat, (float*)d_out);
}

// round 5
// speedup vs baseline: 1.0156x; 1.0156x over previous
#include <cuda_runtime.h>

#define HH 128
#define WW 128
#define CC 16
#define FF 16
#define CF (CC * FF)
#define NB 2
#define SNX 32
#define SNY 32

// ratio[b][snx][sny][c*16+f] : 2*32*32*256 floats = 2 MB
__device__ float g_ratio[(size_t)NB * SNX * SNY * CF];

// ---------------------------------------------------------------------------
// Kernel 1: per 4x2 patch octet (snx = 4I..4I+3, sny = 2J..2J+1).
// Union extent: rows 16I-2 .. 16I+17 (20), cols 8J-2 .. 8J+9 (12).
// Thread t owns cf index t (c = t>>4): accumulators fully in registers.
// ---------------------------------------------------------------------------
__global__ __launch_bounds__(256) void ratio_kernel(
    const float* __restrict__ pet, const float* __restrict__ bfeat)
{
    __shared__ float pet_s[20 * 12 * CC];   // 15 KB

    const int J  = blockIdx.x;   // 0..15
    const int I  = blockIdx.y;   // 0..7
    const int bz = blockIdx.z;
    const int t  = threadIdx.x;
    const int c  = t >> 4;

    const int r0 = 16 * I - 2;
    const int c0 = 8 * J - 2;

    // stage pet for the 20x12 union (zero outside image)
    for (int idx = t; idx < 20 * 12 * CC; idx += 256) {
        int pix = idx >> 4, cc = idx & 15;
        int u = pix / 12, v = pix - u * 12;
        int r = r0 + u, col = c0 + v;
        float val = 0.f;
        if ((unsigned)r < HH && (unsigned)col < WW)
            val = pet[((bz * HH + r) * WW + col) * CC + cc];
        pet_s[idx] = val;
    }
    __syncthreads();

    float d[4][2]  = {};
    float kk[4][2] = {};
    const float* bb = bfeat + (size_t)bz * HH * WW * CF + t;

#pragma unroll
    for (int u = 0; u < 20; u++) {
        int r = r0 + u;
        bool rowok = (unsigned)r < HH;
        float rd0 = 0.f, rd1 = 0.f, rk0 = 0.f, rk1 = 0.f;
#pragma unroll
        for (int v = 0; v < 12; v++) {
            int col = c0 + v;
            float bv = 0.f;
            if (rowok && (unsigned)col < WW)
                bv = __ldg(bb + (r * WW + col) * CF);
            float pv = pet_s[(u * 12 + v) * CC + c];
            float pb = pv * bv;
            if (v < 8)  { rd0 += bv; rk0 += pb; }   // y-window q=0
            if (v >= 4) { rd1 += bv; rk1 += pb; }   // y-window q=1
        }
        // x-windows containing row u: p = u>>2 and (u>>2)-1 (compile-time)
        int p1 = u >> 2;
        if (p1 <= 3) { d[p1][0] += rd0; d[p1][1] += rd1;
                       kk[p1][0] += rk0; kk[p1][1] += rk1; }
        int p0 = p1 - 1;
        if (p0 >= 0) { d[p0][0] += rd0; d[p0][1] += rd1;
                       kk[p0][0] += rk0; kk[p0][1] += rk1; }
    }

#pragma unroll
    for (int p = 0; p < 4; p++)
#pragma unroll
        for (int q = 0; q < 2; q++) {
            float rat = (d[p][q] != 0.f) ? (kk[p][q] / d[p][q]) : 0.f;
            int snx = 4 * I + p, sny = 2 * J + q;
            g_ratio[(((size_t)bz * SNX + snx) * SNY + sny) * CF + t] = rat;
        }
}

// ---------------------------------------------------------------------------
// Kernel 2: out(x,y,c) = 0.25 * sum_f b[x,y,c,f] * S(c,f)
// CTA = 8x4 output tile: x-block a (4 px) x two y-blocks {2*A2, 2*A2+1} (8 px).
// Each thread handles 2 pixels (j and j+4) -> 8 float4 loads in flight.
// ---------------------------------------------------------------------------
__global__ __launch_bounds__(256) void apply_kernel(
    const float* __restrict__ bfeat, float* __restrict__ out)
{
    __shared__ float S2[2][CF];   // [s][f*16+c]

    const int A2 = blockIdx.x;   // 0..16 (y-block pair)
    const int a  = blockIdx.y;   // 0..32 (x-block)
    const int bz = blockIdx.z;
    const int t  = threadIdx.x;

    // S for each of the two y-blocks
#pragma unroll
    for (int s = 0; s < 2; s++) {
        int blk = 2 * A2 + s;
        float acc = 0.f;
#pragma unroll
        for (int da = 0; da < 2; da++) {
            int snx = a - 1 + da;
            if ((unsigned)snx >= SNX) continue;
#pragma unroll
            for (int db = 0; db < 2; db++) {
                int sny = blk - 1 + db;
                if ((unsigned)sny >= SNY) continue;
                acc += g_ratio[(((size_t)bz * SNX + snx) * SNY + sny) * CF + t];
            }
        }
        S2[s][(t & 15) * CC + (t >> 4)] = acc;   // transposed store
    }
    __syncthreads();

    const int c2  = t & 15;
    const int pix = t >> 4;             // 0..15
    const int i = pix >> 2, j = pix & 3;
    const int x  = 4 * a - 2 + i;
    const int y0 = 8 * A2 - 2 + j;
    const int y1 = y0 + 4;

    const bool okx = (unsigned)x < HH;
    const bool ok0 = okx && (unsigned)y0 < WW;
    const bool ok1 = okx && (unsigned)y1 < WW;

    const float* base = bfeat + (size_t)(bz * HH + x) * WW * CF + c2 * FF;

    float4 b0[4], b1[4];
#pragma unroll
    for (int q = 0; q < 4; q++) b0[q] = make_float4(0.f, 0.f, 0.f, 0.f);
#pragma unroll
    for (int q = 0; q < 4; q++) b1[q] = make_float4(0.f, 0.f, 0.f, 0.f);
    if (ok0) {
        const float4* p = (const float4*)(base + (size_t)y0 * CF);
#pragma unroll
        for (int q = 0; q < 4; q++) b0[q] = __ldg(p + q);
    }
    if (ok1) {
        const float4* p = (const float4*)(base + (size_t)y1 * CF);
#pragma unroll
        for (int q = 0; q < 4; q++) b1[q] = __ldg(p + q);
    }

    float dot0 = 0.f, dot1 = 0.f;
#pragma unroll
    for (int q = 0; q < 4; q++) {
        dot0 = fmaf(b0[q].x, S2[0][(4 * q + 0) * CC + c2],
               fmaf(b0[q].y, S2[0][(4 * q + 1) * CC + c2],
               fmaf(b0[q].z, S2[0][(4 * q + 2) * CC + c2],
               fmaf(b0[q].w, S2[0][(4 * q + 3) * CC + c2], dot0))));
        dot1 = fmaf(b1[q].x, S2[1][(4 * q + 0) * CC + c2],
               fmaf(b1[q].y, S2[1][(4 * q + 1) * CC + c2],
               fmaf(b1[q].z, S2[1][(4 * q + 2) * CC + c2],
               fmaf(b1[q].w, S2[1][(4 * q + 3) * CC + c2], dot1))));
    }
    if (ok0) out[((bz * HH + x) * WW + y0) * CC + c2] = 0.25f * dot0;
    if (ok1) out[((bz * HH + x) * WW + y1) * CC + c2] = 0.25f * dot1;
}

extern "C" void kernel_launch(void* const* d_in, const int* in_sizes, int n_in,
                              void* d_out, int out_size)
{
    // Input order per reference signature: mr (unused), pet, b, px, py, sx, sy
    const float* pet   = (const float*)d_in[1];
    const float* bfeat = (const float*)d_in[2];

    dim3 grid1(SNY / 2, SNX / 4, NB);        // 16 x 8 x 2 octets
    ratio_kernel<<<grid1, 256>>>(pet, bfeat);

    dim3 grid2(17, 33, NB);                  // y-pairs x x-blocks
    apply_kernel<<<grid2, 256>>>(bfeat, (float*)d_out);
}

// round 6
// speedup vs baseline: 1.1495x; 1.1318x over previous
#include <cuda_runtime.h>

#define HH 128
#define WW 128
#define CC 16
#define FF 16
#define CF (CC * FF)
#define NB 2
#define SNX 32
#define SNY 32

// ratio[b][snx][sny][c*16+f] : 2*32*32*256 floats = 2 MB
__device__ float g_ratio[(size_t)NB * SNX * SNY * CF];

// ---------------------------------------------------------------------------
// Kernel 1: per 4x4 patch tile (snx = 4I..4I+3, sny = 4J..4J+3).
// Union extent: rows 16I-2..16I+17 (20), cols 16J-2..16J+17 (20).
// Thread t owns cf index t (c = t>>4): 32 window accumulators in registers.
// ---------------------------------------------------------------------------
__global__ __launch_bounds__(256) void ratio_kernel(
    const float* __restrict__ pet, const float* __restrict__ bfeat)
{
    __shared__ float pet_s[20 * 20 * CC];   // 25.6 KB

    const int J  = blockIdx.x;   // 0..7
    const int I  = blockIdx.y;   // 0..7
    const int bz = blockIdx.z;
    const int t  = threadIdx.x;
    const int c  = t >> 4;

    const int r0 = 16 * I - 2;
    const int c0 = 16 * J - 2;

    // stage pet for the 20x20 union (zero outside image)
    for (int idx = t; idx < 20 * 20 * CC; idx += 256) {
        int pix = idx >> 4, cc = idx & 15;
        int u = pix / 20, v = pix - u * 20;
        int r = r0 + u, col = c0 + v;
        float val = 0.f;
        if ((unsigned)r < HH && (unsigned)col < WW)
            val = pet[((bz * HH + r) * WW + col) * CC + cc];
        pet_s[idx] = val;
    }
    __syncthreads();

    float d[4][4]  = {};
    float kk[4][4] = {};
    const float* bb = bfeat + (size_t)bz * HH * WW * CF + t;

#pragma unroll
    for (int u = 0; u < 20; u++) {
        const int r = r0 + u;
        const bool rowok = (unsigned)r < HH;
        float rd[4] = {}, rk[4] = {};
#pragma unroll
        for (int v = 0; v < 20; v++) {
            const int col = c0 + v;
            float bv = 0.f;
            if (rowok && (unsigned)col < WW)
                bv = __ldg(bb + (r * WW + col) * CF);
            float pv = pet_s[(u * 20 + v) * CC + c];
            float pb = pv * bv;
            const int q1 = v >> 2;           // compile-time
            if (q1 <= 3)      { rd[q1] += bv;     rk[q1] += pb; }
            if (q1 - 1 >= 0)  { rd[q1 - 1] += bv; rk[q1 - 1] += pb; }
        }
        const int p1 = u >> 2;               // compile-time
        if (p1 <= 3) {
#pragma unroll
            for (int q = 0; q < 4; q++) { d[p1][q] += rd[q]; kk[p1][q] += rk[q]; }
        }
        if (p1 - 1 >= 0) {
#pragma unroll
            for (int q = 0; q < 4; q++) { d[p1 - 1][q] += rd[q]; kk[p1 - 1][q] += rk[q]; }
        }
    }

#pragma unroll
    for (int p = 0; p < 4; p++)
#pragma unroll
        for (int q = 0; q < 4; q++) {
            float rat = (d[p][q] != 0.f) ? (kk[p][q] / d[p][q]) : 0.f;
            int snx = 4 * I + p, sny = 4 * J + q;
            g_ratio[(((size_t)bz * SNX + snx) * SNY + sny) * CF + t] = rat;
        }
}

// ---------------------------------------------------------------------------
// Kernel 2: out(x,y,c) = 0.25 * sum_f b[x,y,c,f] * S(c,f)
// CTA = 4x8 output tile. 64 threads per pixel (contiguous float4 slots ->
// fully coalesced LDG.128), 8 pixels per thread in flight, 4-lane shfl dot.
// ---------------------------------------------------------------------------
__global__ __launch_bounds__(256) void apply_kernel(
    const float* __restrict__ bfeat, float* __restrict__ out)
{
    __shared__ float S2[2][CF];   // natural layout [c*16 + f]

    const int A2 = blockIdx.x;   // 0..16 (y-block pair)
    const int a  = blockIdx.y;   // 0..32 (x-block)
    const int bz = blockIdx.z;
    const int t  = threadIdx.x;

    // S for each of the two y-blocks (coalesced ratio reads, natural store)
#pragma unroll
    for (int s = 0; s < 2; s++) {
        int blk = 2 * A2 + s;
        float acc = 0.f;
#pragma unroll
        for (int da = 0; da < 2; da++) {
            int snx = a - 1 + da;
            if ((unsigned)snx >= SNX) continue;
#pragma unroll
            for (int db = 0; db < 2; db++) {
                int sny = blk - 1 + db;
                if ((unsigned)sny >= SNY) continue;
                acc += g_ratio[(((size_t)bz * SNX + snx) * SNY + sny) * CF + t];
            }
        }
        S2[s][t] = acc;
    }
    __syncthreads();

    const int q  = t & 63;       // float4 slot within pixel
    const int pg = t >> 6;       // x-row i = pg (0..3)
    const int c  = q >> 2;
    const int f4 = q & 3;

    const int x = 4 * a - 2 + pg;
    const bool okx = (unsigned)x < HH;
    const float* rowbase = bfeat + ((size_t)(bz * HH + x) * WW) * CF + q * 4;

    // batch all 8 pixel loads (j = 0..7)
    float4 bv[8];
#pragma unroll
    for (int m = 0; m < 8; m++) {
        int y = 8 * A2 - 2 + m;
        bv[m] = make_float4(0.f, 0.f, 0.f, 0.f);
        if (okx && (unsigned)y < WW)
            bv[m] = __ldg((const float4*)(rowbase + (size_t)y * CF));
    }

    const bool lead = ((q & 3) == 0);
#pragma unroll
    for (int m = 0; m < 8; m++) {
        int y = 8 * A2 - 2 + m;
        const int s = m >> 2;
        const float4 sv = *(const float4*)(&S2[s][c * 16 + f4 * 4]);
        float dot = bv[m].x * sv.x + bv[m].y * sv.y + bv[m].z * sv.z + bv[m].w * sv.w;
        dot += __shfl_xor_sync(0xffffffffu, dot, 1);
        dot += __shfl_xor_sync(0xffffffffu, dot, 2);
        if (lead && okx && (unsigned)y < WW)
            out[((bz * HH + x) * WW + y) * CC + c] = 0.25f * dot;
    }
}

extern "C" void kernel_launch(void* const* d_in, const int* in_sizes, int n_in,
                              void* d_out, int out_size)
{
    // Input order per reference signature: mr (unused), pet, b, px, py, sx, sy
    const float* pet   = (const float*)d_in[1];
    const float* bfeat = (const float*)d_in[2];

    dim3 grid1(SNY / 4, SNX / 4, NB);        // 8 x 8 x 2 tiles
    ratio_kernel<<<grid1, 256>>>(pet, bfeat);

    dim3 grid2(17, 33, NB);                  // y-pairs x x-blocks
    apply_kernel<<<grid2, 256>>>(bfeat, (float*)d_out);
}